// round 1
// baseline (speedup 1.0000x reference)
#include <cuda_runtime.h>
#include <cuda_fp16.h>

#define B 32
#define R 5
#define C 100
#define N 101
#define H 128
#define E 5
#define F 13      // 8 + R
#define TN 8      // nodes per iter-CTA
#define NT 13     // ceil(N / TN)

// ---------------- scratch (device globals; no allocations allowed) ----------
__device__ __half g_pemb[(size_t)B * N * C * H];   // 82.7 MB, fp16, L2-resident
__device__ float  g_pres[(size_t)B * C * N];       // presence [B,C,N]
__device__ float  g_fx  [(size_t)B * N * H];       // fx1 then fx2
__device__ float  g_ua  [(size_t)B * N * H];       // state ping
__device__ float  g_ub  [(size_t)B * N * H];       // state pong

// ---------------- features: x -> fx1, u = relu(fx1 + bl1) -------------------
__global__ void k_features(const float* __restrict__ ap, const float* __restrict__ act,
                           const float* __restrict__ xa, const float* __restrict__ xb,
                           const float* __restrict__ coord, const float* __restrict__ avail,
                           const float* __restrict__ wx1, const float* __restrict__ bx1,
                           const float* __restrict__ bl1)
{
    int b = blockIdx.x / N, n = blockIdx.x % N;
    __shared__ float xs[F];
    int tid = threadIdx.x;
    if (tid < 5) {
        float s = 0.f;
        #pragma unroll
        for (int r = 0; r < R; r++) {
            int idx = (b * R + r) * N + n;
            float a = ap[idx] + act[idx];
            s = fmaf(a, xa[idx * R + tid], s);
        }
        xs[tid] = s;
    } else if (tid < 10) {
        xs[tid] = xb[(b * N + n) * 5 + tid - 5];
    } else if (tid < 12) {
        xs[tid] = coord[(b * N + n) * 2 + tid - 10];
    } else if (tid == 12) {
        xs[12] = avail[b * N + n];
    }
    __syncthreads();
    int h = tid;
    float acc = bx1[h];
    #pragma unroll
    for (int k = 0; k < F; k++) acc = fmaf(xs[k], wx1[k * H + h], acc);
    int o = (b * N + n) * H + h;
    g_fx[o] = acc;
    g_ua[o] = fmaxf(acc + bl1[h], 0.f);
}

// ---------------- presence head: softmax over n per (b,c) -------------------
__global__ void k_presence(const float* __restrict__ edge, const float* __restrict__ avail,
                           const float* __restrict__ w1p, const float* __restrict__ b1p,
                           const float* __restrict__ w2p, const float* __restrict__ b2p)
{
    int b = blockIdx.x / C, c = blockIdx.x % C;
    __shared__ float w1s[E * H], b1s[H], w2s[H], lg[N], red[H];
    int tid = threadIdx.x;
    for (int i = tid; i < E * H; i += H) w1s[i] = w1p[i];
    b1s[tid] = b1p[tid];
    w2s[tid] = w2p[tid];
    __syncthreads();

    float lgv = -3.4e38f;
    if (tid < N) {
        int n = tid;
        const float* e5 = edge + ((size_t)(b * C + c) * N + n) * E;
        float e0 = e5[0], e1 = e5[1], e2 = e5[2], e3 = e5[3], e4 = e5[4];
        float s = 0.f;
        #pragma unroll 4
        for (int h = 0; h < H; h++) {
            float a = b1s[h];
            a = fmaf(e0, w1s[h], a);
            a = fmaf(e1, w1s[H + h], a);
            a = fmaf(e2, w1s[2 * H + h], a);
            a = fmaf(e3, w1s[3 * H + h], a);
            a = fmaf(e4, w1s[4 * H + h], a);
            s = fmaf(fmaxf(a, 0.f), w2s[h], s);
        }
        s = s + b2p[0];                  // TAU = 1
        float m = avail[b * N + n];
        if (n == c || n == N - 1) m = 0.f;
        lgv = s * m - (1.f - m) * 1e10f;
        lg[n] = lgv;
    }
    red[tid] = lgv;
    __syncthreads();
    for (int s2 = 64; s2 > 0; s2 >>= 1) {
        if (tid < s2) red[tid] = fmaxf(red[tid], red[tid + s2]);
        __syncthreads();
    }
    float mx = red[0];
    __syncthreads();
    float p = 0.f;
    if (tid < N) p = __expf(lg[tid] - mx);
    red[tid] = p;
    __syncthreads();
    for (int s2 = 64; s2 > 0; s2 >>= 1) {
        if (tid < s2) red[tid] += red[tid + s2];
        __syncthreads();
    }
    float inv = 1.f / red[0];
    if (tid < N) {
        float availc = avail[b * N + c];
        g_pres[(size_t)(b * C + c) * N + tid] = availc * p * inv;
    }
}

// ---------------- pemb = presence * tanh(edge @ we + be), fp16 --------------
__global__ void k_pemb(const float* __restrict__ edge, const float* __restrict__ we,
                       const float* __restrict__ be)
{
    int b = blockIdx.x / N, n = blockIdx.x % N;
    __shared__ float wes[E * H], bes[H], es[C * E], ps[C];
    int tid = threadIdx.x;
    for (int i = tid; i < E * H; i += H) wes[i] = we[i];
    bes[tid] = be[tid];
    for (int i = tid; i < C * E; i += H) {
        int c = i / E, e = i % E;
        es[i] = edge[((size_t)(b * C + c) * N + n) * E + e];
    }
    for (int i = tid; i < C; i += H) ps[i] = g_pres[(size_t)(b * C + i) * N + n];
    __syncthreads();
    int h = tid;
    __half* out = g_pemb + ((size_t)(b * N + n) * C) * H + h;
    #pragma unroll 2
    for (int c = 0; c < C; c++) {
        const float* e5 = es + c * E;
        float a = bes[h];
        a = fmaf(e5[0], wes[h], a);
        a = fmaf(e5[1], wes[H + h], a);
        a = fmaf(e5[2], wes[2 * H + h], a);
        a = fmaf(e5[3], wes[3 * H + h], a);
        a = fmaf(e5[4], wes[4 * H + h], a);
        out[(size_t)c * H] = __float2half(ps[c] * tanhf(a));
    }
}

// ---------------- message-passing iteration (fused einsum + wl GEMM) --------
__global__ void k_iter(const float* __restrict__ wl, const float* __restrict__ bl, int dir)
{
    const float* u_in = dir ? g_ub : g_ua;
    float* u_out      = dir ? g_ua : g_ub;
    int b = blockIdx.x / NT, nt = blockIdx.x % NT;
    extern __shared__ char sm[];
    __half2* us = (__half2*)sm;                         // C*64 half2  (25600 B)
    float* wls  = (float*)(sm + C * 64 * 4);            // H*H floats  (65536 B)
    float* ls   = (float*)(sm + C * 64 * 4 + H * H * 4);// TN*H floats (4096 B)
    int tid = threadIdx.x;

    const float2* u2 = (const float2*)(u_in) + (size_t)b * N * 64;
    for (int i = tid; i < C * 64; i += TN * 64)
        us[i] = __float22half2_rn(u2[i]);
    const float4* w4 = (const float4*)wl;
    float4* ws4 = (float4*)wls;
    for (int i = tid; i < H * H / 4; i += TN * 64) ws4[i] = w4[i];
    __syncthreads();

    int h2 = tid & 63, nl = tid >> 6;
    int n = nt * TN + nl;
    float ax = 0.f, ay = 0.f;
    if (n < N) {
        const __half2* pp = (const __half2*)g_pemb + ((size_t)(b * N + n) * C) * 64 + h2;
        #pragma unroll 5
        for (int c = 0; c < C; c++) {
            float2 pf = __half22float2(pp[c * 64]);
            float2 uf = __half22float2(us[c * 64 + h2]);
            ax = fmaf(pf.x, uf.x, ax);
            ay = fmaf(pf.y, uf.y, ay);
        }
    }
    ls[nl * H + 2 * h2]     = ax;
    ls[nl * H + 2 * h2 + 1] = ay;
    __syncthreads();

    float ox = 0.f, oy = 0.f;
    const float2* wv2 = (const float2*)wls;
    #pragma unroll 8
    for (int hp = 0; hp < H; hp++) {
        float lv = ls[nl * H + hp];
        float2 wv = wv2[hp * 64 + h2];
        ox = fmaf(lv, wv.x, ox);
        oy = fmaf(lv, wv.y, oy);
    }
    if (n < N) {
        int base = (b * N + n) * H + 2 * h2;
        float2 r;
        r.x = fmaxf(ox + bl[2 * h2]     + g_fx[base],     0.f);
        r.y = fmaxf(oy + bl[2 * h2 + 1] + g_fx[base + 1], 0.f);
        ((float2*)u_out)[(b * N + n) * 64 + h2] = r;
    }
}

// ---------------- fx2 = u@wx2+bx2; gamma_init = relu(fx2+bl2) ---------------
__global__ void k_fx2(const float* __restrict__ wx2, const float* __restrict__ bx2,
                      const float* __restrict__ bl2)
{
    int b = blockIdx.x >> 2, q = blockIdx.x & 3;
    extern __shared__ char sm[];
    float* wxs = (float*)sm;                 // H*H
    float* ur  = (float*)(sm + H * H * 4);   // 2*H
    int tid = threadIdx.x;                   // 256
    const float4* w4 = (const float4*)wx2;
    float4* s4 = (float4*)wxs;
    for (int i = tid; i < H * H / 4; i += 256) s4[i] = w4[i];
    int h = tid & 127, nl = tid >> 7;
    for (int j = 0; j < 26; j += 2) {
        int n = q * 26 + j + nl;
        __syncthreads();
        if (n < N) ur[nl * H + h] = g_ua[(b * N + n) * H + h];
        __syncthreads();
        if (n < N) {
            float acc = bx2[h];
            #pragma unroll 8
            for (int hp = 0; hp < H; hp++)
                acc = fmaf(ur[nl * H + hp], wxs[hp * H + h], acc);
            int idx = (b * N + n) * H + h;
            g_fx[idx] = acc;
            g_ua[idx] = fmaxf(acc + bl2[h], 0.f);
        }
    }
}

// ---------------- Q readout --------------------------------------------------
__global__ void k_reduce(const float* __restrict__ avail, const float* __restrict__ wQ,
                         float* __restrict__ out)
{
    int b = blockIdx.x;
    int h = threadIdx.x;
    float s = 0.f;
    for (int n = 0; n < N; n++)
        s = fmaf(g_ua[(b * N + n) * H + h], avail[b * N + n], s);
    s *= wQ[h];
    __shared__ float red[H];
    red[h] = s;
    __syncthreads();
    for (int s2 = 64; s2 > 0; s2 >>= 1) {
        if (h < s2) red[h] += red[h + s2];
        __syncthreads();
    }
    if (h == 0) out[b] = red[0];
}

// ---------------- launch -----------------------------------------------------
extern "C" void kernel_launch(void* const* d_in, const int* in_sizes, int n_in,
                              void* d_out, int out_size)
{
    const float* ap    = (const float*)d_in[0];
    const float* act   = (const float*)d_in[1];
    const float* xa    = (const float*)d_in[2];
    const float* xb    = (const float*)d_in[3];
    const float* coord = (const float*)d_in[4];
    const float* edge  = (const float*)d_in[5];
    const float* avail = (const float*)d_in[6];
    const float* w1p   = (const float*)d_in[7];
    const float* b1p   = (const float*)d_in[8];
    const float* w2p   = (const float*)d_in[9];
    const float* b2p   = (const float*)d_in[10];
    const float* wx1   = (const float*)d_in[11];
    const float* bx1   = (const float*)d_in[12];
    const float* we1   = (const float*)d_in[13];
    const float* be1   = (const float*)d_in[14];
    const float* wl1   = (const float*)d_in[15];
    const float* bl1   = (const float*)d_in[16];
    const float* wx2   = (const float*)d_in[17];
    const float* bx2   = (const float*)d_in[18];
    const float* we2   = (const float*)d_in[19];
    const float* be2   = (const float*)d_in[20];
    const float* wl2   = (const float*)d_in[21];
    const float* bl2   = (const float*)d_in[22];
    const float* wQ    = (const float*)d_in[23];
    float* out = (float*)d_out;

    const int iter_smem = C * 64 * 4 + H * H * 4 + TN * H * 4;  // 95232 B
    const int fx2_smem  = H * H * 4 + 2 * H * 4;                // 66560 B
    cudaFuncSetAttribute(k_iter, cudaFuncAttributeMaxDynamicSharedMemorySize, iter_smem);
    cudaFuncSetAttribute(k_fx2,  cudaFuncAttributeMaxDynamicSharedMemorySize, fx2_smem);

    k_features<<<B * N, H>>>(ap, act, xa, xb, coord, avail, wx1, bx1, bl1);
    k_presence<<<B * C, H>>>(edge, avail, w1p, b1p, w2p, b2p);

    // round 1 (iteration 1 folded into k_features init; 4 full sweeps)
    k_pemb<<<B * N, H>>>(edge, we1, be1);
    k_iter<<<B * NT, TN * 64, iter_smem>>>(wl1, bl1, 0);
    k_iter<<<B * NT, TN * 64, iter_smem>>>(wl1, bl1, 1);
    k_iter<<<B * NT, TN * 64, iter_smem>>>(wl1, bl1, 0);
    k_iter<<<B * NT, TN * 64, iter_smem>>>(wl1, bl1, 1);

    // round 2
    k_fx2<<<B * 4, 256, fx2_smem>>>(wx2, bx2, bl2);
    k_pemb<<<B * N, H>>>(edge, we2, be2);
    k_iter<<<B * NT, TN * 64, iter_smem>>>(wl2, bl2, 0);
    k_iter<<<B * NT, TN * 64, iter_smem>>>(wl2, bl2, 1);
    k_iter<<<B * NT, TN * 64, iter_smem>>>(wl2, bl2, 0);
    k_iter<<<B * NT, TN * 64, iter_smem>>>(wl2, bl2, 1);

    k_reduce<<<B, H>>>(avail, wQ, out);
}